// round 14
// baseline (speedup 1.0000x reference)
#include <cuda_runtime.h>
#include <cuda_fp16.h>
#include <math.h>
#include <stdint.h>

#define S_LEN 3072
#define DMODEL 1280
#define NHEAD 16
#define HDIM 80
#define FFDIM 5120

// ---------------- scratch (device globals; no allocations allowed) ----------
__device__ __half g_hh[S_LEN * DMODEL];        // LN output (fp16)
__device__ __half g_qkvh[S_LEN * 3 * DMODEL];  // QKV (fp16)
__device__ __half g_qh[S_LEN * DMODEL];        // rope'd Q (fp16)
__device__ __half g_kh[S_LEN * DMODEL];        // rope'd K (fp16)
__device__ __half g_vth[NHEAD * HDIM * S_LEN]; // V^T [h][d][s] (fp16)
__device__ __half g_attnh[S_LEN * DMODEL];     // attention output (fp16)
__device__ float  g_x1[S_LEN * DMODEL];        // x + proj(attn)  (fp32)
__device__ __half g_ffh[S_LEN * FFDIM];        // gelu(fc1) (fp16)
__device__ __half g_wh_qkv[3 * DMODEL * DMODEL];  // weights [N][K] fp16
__device__ __half g_wh_proj[DMODEL * DMODEL];
__device__ __half g_wh_fc1[FFDIM * DMODEL];
__device__ __half g_wh_fc2[DMODEL * FFDIM];

// ---------------- helpers ----------------
__device__ __forceinline__ uint32_t smem_u32(const void* p) {
    uint32_t a;
    asm("{ .reg .u64 t; cvta.to.shared.u64 t, %1; cvt.u32.u64 %0, t; }"
        : "=r"(a) : "l"(p));
    return a;
}

#define CP_ASYNC16(dst, src) \
    asm volatile("cp.async.cg.shared.global [%0], [%1], 16;" :: "r"(dst), "l"(src) : "memory")
#define CP_COMMIT() asm volatile("cp.async.commit_group;" ::: "memory")
#define CP_WAIT2()  asm volatile("cp.async.wait_group 2;" ::: "memory")
#define CP_WAIT0()  asm volatile("cp.async.wait_group 0;" ::: "memory")

// fp16 mma: D(f32) += A(f16 m16k16,row) * B(f16 k16n8,col)
__device__ __forceinline__ void mma_f16(float* c, const uint32_t* a, const uint32_t* b) {
    asm volatile(
        "mma.sync.aligned.m16n8k16.row.col.f32.f16.f16.f32 "
        "{%0,%1,%2,%3}, {%4,%5,%6,%7}, {%8,%9}, {%0,%1,%2,%3};"
        : "+f"(c[0]), "+f"(c[1]), "+f"(c[2]), "+f"(c[3])
        : "r"(a[0]), "r"(a[1]), "r"(a[2]), "r"(a[3]), "r"(b[0]), "r"(b[1]));
}

__device__ __forceinline__ void ldsm_x4(uint32_t* r, uint32_t addr) {
    asm volatile("ldmatrix.sync.aligned.m8n8.x4.shared.b16 {%0,%1,%2,%3}, [%4];"
                 : "=r"(r[0]), "=r"(r[1]), "=r"(r[2]), "=r"(r[3]) : "r"(addr));
}

// ---------------- weight transpose + fp16 convert: in[K,N] -> out[N,K] ----
__global__ __launch_bounds__(256) void transpose_h64(
    const float* __restrict__ in, __half* __restrict__ out, int K, int N)
{
    __shared__ float t[64][65];
    int n0 = blockIdx.x * 64, k0 = blockIdx.y * 64;
    int tid = threadIdx.x;
#pragma unroll
    for (int it = 0; it < 16; it++) {
        int idx = tid + it * 256;
        int r = idx >> 6, c = idx & 63;
        t[r][c] = in[(size_t)(k0 + r) * N + n0 + c];
    }
    __syncthreads();
#pragma unroll
    for (int it = 0; it < 16; it++) {
        int idx = tid + it * 256;
        int j = idx >> 6, i = idx & 63;
        out[(size_t)(n0 + j) * K + k0 + i] = __float2half_rn(t[i][j]);
    }
}

// ---------------- fp16 mma GEMM: C = A[M,K] @ Bt[N,K]^T + bias ------------
// BM=128, BN=256, BK=32, 4 stages, 256 threads (8 warps 2x4), warp tile 64x64.
// ldmatrix.x4 operand loads (A per-mt, B per-nt-pair).
#define RSTR 80                       // smem row stride, bytes
#define A_BYTES (128 * RSTR)          // 10240
#define B_BYTES (256 * RSTR)          // 20480
#define STG_BYTES (A_BYTES + B_BYTES) // 30720
#define NSTAGE 4

template <int ACT, int RES, int OUTH>
__global__ __launch_bounds__(256, 1)
void gemm_h(const __half* __restrict__ A, const __half* __restrict__ Bt,
            const float* __restrict__ bias, const float* __restrict__ res,
            void* __restrict__ Cv, int M, int N, int K)
{
    extern __shared__ __align__(16) char smem[];
    const uint32_t sb = smem_u32(smem);
    const int tid = threadIdx.x;
    const int wid = tid >> 5, lane = tid & 31;
    const int g = lane >> 2, t = lane & 3;
    const int warp_m = (wid >> 2) * 64;
    const int warp_n = (wid & 3) * 64;
    const int m0 = blockIdx.y * 128;
    const int n0 = blockIdx.x * 256;
    const int nk = K / 32;

    // ldmatrix lane-address components
    const int lrow = lane & 7;
    const int lt   = lane >> 3;                  // 0..3: tile select
    const uint32_t a_lane_off =                  // A x4: tiles (m,k),(m+8,k),(m,k+16),(m+8,k+16)
        (uint32_t)((lrow + ((lt & 1) << 3)) * RSTR + ((lt & 2) << 3));
    const uint32_t b_lane_off =                  // B x4: tiles (n,k),(n+8,k),(n,k+16),(n+8,k+16)
        (uint32_t)((lrow + ((lt & 1) << 3)) * RSTR + ((lt & 2) << 3));

    float c[4][8][4];
#pragma unroll
    for (int mt = 0; mt < 4; mt++)
#pragma unroll
        for (int nt = 0; nt < 8; nt++)
#pragma unroll
            for (int i = 0; i < 4; i++) c[mt][nt][i] = 0.f;

    auto load_tile = [&](int stage, int k0) {
        uint32_t sA = sb + (uint32_t)stage * STG_BYTES;
        uint32_t sB = sA + A_BYTES;
#pragma unroll
        for (int cc = 0; cc < 2; cc++) {
            int idx = tid + cc * 256;
            int row = idx >> 2, off = idx & 3;
            CP_ASYNC16(sA + (uint32_t)row * RSTR + (uint32_t)off * 16,
                       (const char*)(A + (size_t)(m0 + row) * K + k0) + off * 16);
        }
#pragma unroll
        for (int cc = 0; cc < 4; cc++) {
            int idx = tid + cc * 256;
            int row = idx >> 2, off = idx & 3;
            CP_ASYNC16(sB + (uint32_t)row * RSTR + (uint32_t)off * 16,
                       (const char*)(Bt + (size_t)(n0 + row) * K + k0) + off * 16);
        }
    };

    int k0 = 0;
#pragma unroll
    for (int s = 0; s < NSTAGE - 1; s++) {
        load_tile(s, k0);
        CP_COMMIT();
        k0 += 32;
    }

    for (int it = 0; it < nk; it++) {
        CP_WAIT2();
        __syncthreads();
        const int cur = it & (NSTAGE - 1);
        if (k0 < K) {
            load_tile((it + NSTAGE - 1) & (NSTAGE - 1), k0);
            k0 += 32;
        }
        CP_COMMIT();

        const uint32_t As = sb + (uint32_t)cur * STG_BYTES;
        const uint32_t Bs = As + A_BYTES;

#pragma unroll
        for (int kk = 0; kk < 2; kk++) {
            const uint32_t kb = kk * 32;
            uint32_t a[4][4], b[8][2];
#pragma unroll
            for (int mt = 0; mt < 4; mt++)
                ldsm_x4(a[mt], As + (uint32_t)(warp_m + mt * 16) * RSTR + kb + a_lane_off);
#pragma unroll
            for (int p = 0; p < 4; p++) {
                uint32_t r[4];
                ldsm_x4(r, Bs + (uint32_t)(warp_n + p * 16) * RSTR + kb + b_lane_off);
                b[2 * p][0]     = r[0];
                b[2 * p + 1][0] = r[1];
                b[2 * p][1]     = r[2];
                b[2 * p + 1][1] = r[3];
            }
#pragma unroll
            for (int mt = 0; mt < 4; mt++)
#pragma unroll
                for (int nt = 0; nt < 8; nt++)
                    mma_f16(c[mt][nt], a[mt], b[nt]);
        }
    }

#pragma unroll
    for (int mt = 0; mt < 4; mt++) {
        const int rm = m0 + warp_m + mt * 16 + g;
#pragma unroll
        for (int nt = 0; nt < 8; nt++) {
            const int cn = n0 + warp_n + nt * 8 + 2 * t;
            float2 bv = *(const float2*)(bias + cn);
            float v0 = c[mt][nt][0] + bv.x;
            float v1 = c[mt][nt][1] + bv.y;
            float v2 = c[mt][nt][2] + bv.x;
            float v3 = c[mt][nt][3] + bv.y;
            if (RES) {
                float2 r0 = *(const float2*)(res + (size_t)rm * N + cn);
                float2 r1 = *(const float2*)(res + (size_t)(rm + 8) * N + cn);
                v0 += r0.x; v1 += r0.y; v2 += r1.x; v3 += r1.y;
            }
            if (ACT) {
                v0 = v0 / (1.f + __expf(-1.702f * v0));
                v1 = v1 / (1.f + __expf(-1.702f * v1));
                v2 = v2 / (1.f + __expf(-1.702f * v2));
                v3 = v3 / (1.f + __expf(-1.702f * v3));
            }
            if (OUTH) {
                __half* C = (__half*)Cv;
                *(__half2*)(C + (size_t)rm * N + cn) =
                    __halves2half2(__float2half_rn(v0), __float2half_rn(v1));
                *(__half2*)(C + (size_t)(rm + 8) * N + cn) =
                    __halves2half2(__float2half_rn(v2), __float2half_rn(v3));
            } else {
                float* C = (float*)Cv;
                *(float2*)(C + (size_t)rm * N + cn)       = make_float2(v0, v1);
                *(float2*)(C + (size_t)(rm + 8) * N + cn) = make_float2(v2, v3);
            }
        }
    }
}

// ---------------- LayerNorm (fp16 output) ----------------
__global__ __launch_bounds__(256) void ln_kernel(
    const float* __restrict__ x, const float* __restrict__ sc,
    const float* __restrict__ bi, __half* __restrict__ out)
{
    int row = blockIdx.x;
    const float* xr = x + row * DMODEL;
    __half* orow = out + (size_t)row * DMODEL;
    int t = threadIdx.x;
    float v[5];
    float s = 0.f, s2 = 0.f;
#pragma unroll
    for (int i = 0; i < 5; i++) {
        v[i] = xr[t + i * 256];
        s += v[i];
        s2 = fmaf(v[i], v[i], s2);
    }
    __shared__ float rs[8], rs2[8];
#pragma unroll
    for (int o = 16; o; o >>= 1) {
        s  += __shfl_xor_sync(0xffffffffu, s, o);
        s2 += __shfl_xor_sync(0xffffffffu, s2, o);
    }
    if ((t & 31) == 0) { rs[t >> 5] = s; rs2[t >> 5] = s2; }
    __syncthreads();
    if (t < 32) {
        float a = (t < 8) ? rs[t] : 0.f;
        float b = (t < 8) ? rs2[t] : 0.f;
#pragma unroll
        for (int o = 4; o; o >>= 1) {
            a += __shfl_xor_sync(0xffffffffu, a, o);
            b += __shfl_xor_sync(0xffffffffu, b, o);
        }
        if (t == 0) { rs[0] = a; rs2[0] = b; }
    }
    __syncthreads();
    float mu = rs[0] * (1.f / DMODEL);
    float var = rs2[0] * (1.f / DMODEL) - mu * mu;
    float inv = rsqrtf(var + 1e-6f);
#pragma unroll
    for (int i = 0; i < 5; i++) {
        int c = t + i * 256;
        orow[c] = __float2half_rn((v[i] - mu) * inv * sc[c] + bi[c]);
    }
}

// ---------------- RoPE: q,k fp16 -> rotated fp16 buffers ----------------
__global__ __launch_bounds__(256) void rope_h_kernel(
    const __half* __restrict__ qkv, const float* __restrict__ rot,
    __half* __restrict__ qh, __half* __restrict__ kh)
{
    int idx = blockIdx.x * 256 + threadIdx.x;
    const int total = S_LEN * 2 * NHEAD * 40;
    if (idx >= total) return;
    int i = idx % 40;
    int h = (idx / 40) % NHEAD;
    int w = (idx / (40 * NHEAD)) % 2;
    int s = idx / (40 * NHEAD * 2);
    const __half* p = qkv + (size_t)s * (3 * DMODEL) + w * DMODEL + h * HDIM;
    __half* dst = (w == 0 ? qh : kh) + (size_t)s * DMODEL + h * HDIM;
    float x1 = __half2float(p[i]);
    float x2 = __half2float(p[i + 40]);
    float f1 = rot[s * 40 + (i >> 1)];
    float f2 = rot[s * 40 + 20 + (i >> 1)];
    float c1, s1, c2, s2v;
    sincosf(f1, &s1, &c1);
    sincosf(f2, &s2v, &c2);
    dst[i]      = __float2half_rn(x1 * c1 - x2 * s1);
    dst[i + 40] = __float2half_rn(x2 * c2 + x1 * s2v);
}

// ---------------- V transpose: qkv fp16 [s][v:h*80+d] -> vth fp16 [h][d][s]
__global__ __launch_bounds__(256) void vtrans_kernel(
    const __half* __restrict__ qkv, __half* __restrict__ vth)
{
    __shared__ float t[HDIM][65];
    int s0 = blockIdx.x * 64;
    int h = blockIdx.y;
    int tid = threadIdx.x;
#pragma unroll
    for (int it = 0; it < 20; it++) {
        int idx = tid + it * 256;
        int sl = idx / 80, d = idx % 80;
        t[d][sl] = __half2float(
            qkv[(size_t)(s0 + sl) * (3 * DMODEL) + 2 * DMODEL + h * HDIM + d]);
    }
    __syncthreads();
#pragma unroll
    for (int it = 0; it < 20; it++) {
        int idx = tid + it * 256;
        int d = idx >> 6, sl = idx & 63;
        vth[(size_t)(h * HDIM + d) * S_LEN + s0 + sl] = __float2half_rn(t[d][sl]);
    }
}

// ---------------- fp16 flash attention (block-diag segments) --------------
#define AQSTR 176   // Q/K smem row stride, bytes
#define AVSTR 144   // VT & P smem row stride, bytes
#define AOFF_Q  0
#define AOFF_K0 11264
#define AOFF_K1 22528
#define AOFF_V0 33792
#define AOFF_V1 45312
#define ATTN_SMEM_BYTES 56832

__global__ __launch_bounds__(128, 1) void attn_h_kernel(
    const __half* __restrict__ qh, const __half* __restrict__ kh,
    const __half* __restrict__ vth, const int* __restrict__ cu,
    int nseg, __half* __restrict__ out)
{
    extern __shared__ __align__(16) char sm[];
    const uint32_t sb = smem_u32(sm);
    const int tid = threadIdx.x;
    const int warp = tid >> 5, lane = tid & 31;
    const int g = lane >> 2, t = lane & 3;
    const int h = blockIdx.y;
    const int q0 = blockIdx.x * 64;
    const int w16 = warp * 16;

    int start = 0, end = S_LEN;
    for (int i = 0; i < nseg; i++) {
        int a = cu[i], b = cu[i + 1];
        if (q0 >= a && q0 < b) { start = a; end = b; break; }
    }
    const int L = end - start;
    const int ntiles = (L + 63) >> 6;

    for (int i = tid; i < 640; i += 128) {
        int row = i / 10, c = i % 10;
        CP_ASYNC16(sb + AOFF_Q + (uint32_t)row * AQSTR + (uint32_t)c * 16,
                   (const char*)(qh + (size_t)(q0 + row) * DMODEL + h * HDIM) + c * 16);
    }
    CP_COMMIT();

    auto load_kv = [&](int stage, int k0) {
        const uint32_t kBase = sb + (stage ? AOFF_K1 : AOFF_K0);
        const uint32_t vBase = sb + (stage ? AOFF_V1 : AOFF_V0);
        for (int i = tid; i < 640; i += 128) {
            int row = i / 10, c = i % 10;
            int key = k0 + row;
            int src = start + (key < L ? key : L - 1);
            CP_ASYNC16(kBase + (uint32_t)row * AQSTR + (uint32_t)c * 16,
                       (const char*)(kh + (size_t)src * DMODEL + h * HDIM) + c * 16);
        }
        for (int i = tid; i < 640; i += 128) {
            int d = i >> 3, c = i & 7;
            int kk0 = k0 + c * 8;
            if (kk0 + 8 > L) kk0 = L - 8;
            CP_ASYNC16(vBase + (uint32_t)d * AVSTR + (uint32_t)c * 16,
                       (const char*)(vth + (size_t)(h * HDIM + d) * S_LEN + start + kk0));
        }
    };

    load_kv(0, 0);
    CP_COMMIT();
    CP_WAIT0();
    __syncthreads();

    uint32_t qf[5][4];
#pragma unroll
    for (int ks = 0; ks < 5; ks++) {
        const char* qp = sm + AOFF_Q + (w16 + g) * AQSTR + ks * 32 + 4 * t;
        qf[ks][0] = *(const uint32_t*)(qp);
        qf[ks][1] = *(const uint32_t*)(qp + 8 * AQSTR);
        qf[ks][2] = *(const uint32_t*)(qp + 16);
        qf[ks][3] = *(const uint32_t*)(qp + 8 * AQSTR + 16);
    }
    __syncthreads();

    if (1 < ntiles) {
        load_kv(1, 64);
    }
    CP_COMMIT();

    const float scale = 0.111803398875f;   // 1/sqrt(80)
    float m[2] = {-1e30f, -1e30f};
    float l[2] = {0.f, 0.f};
    float o[10][4];
#pragma unroll
    for (int nt = 0; nt < 10; nt++)
#pragma unroll
        for (int i = 0; i < 4; i++) o[nt][i] = 0.f;

    char* Pb = sm + AOFF_Q;

    for (int kt = 0; kt < ntiles; kt++) {
        if (kt > 0) {
            CP_WAIT0();
            __syncthreads();
            if (kt + 1 < ntiles) {
                load_kv((kt + 1) & 1, (kt + 1) * 64);
            }
            CP_COMMIT();
        }
        const char* K = sm + ((kt & 1) ? AOFF_K1 : AOFF_K0);
        const char* V = sm + ((kt & 1) ? AOFF_V1 : AOFF_V0);

        float s[8][4];
#pragma unroll
        for (int nt = 0; nt < 8; nt++)
#pragma unroll
            for (int i = 0; i < 4; i++) s[nt][i] = 0.f;
#pragma unroll
        for (int ks = 0; ks < 5; ks++) {
            uint32_t b[8][2];
#pragma unroll
            for (int nt = 0; nt < 8; nt++) {
                const char* kp = K + (nt * 8 + g) * AQSTR + ks * 32 + 4 * t;
                b[nt][0] = *(const uint32_t*)(kp);
                b[nt][1] = *(const uint32_t*)(kp + 16);
            }
#pragma unroll
            for (int nt = 0; nt < 8; nt++)
                mma_f16(s[nt], qf[ks], b[nt]);
        }

        const bool maskT = (kt == ntiles - 1) && (L & 63);
#pragma unroll
        for (int r = 0; r < 2; r++) {
            float mx = -1e30f;
#pragma unroll
            for (int nt = 0; nt < 8; nt++) {
                float v0 = s[nt][2 * r]     * scale;
                float v1 = s[nt][2 * r + 1] * scale;
                if (maskT) {
                    int col = kt * 64 + nt * 8 + 2 * t;
                    if (col >= L)     v0 = -1e30f;
                    if (col + 1 >= L) v1 = -1e30f;
                }
                s[nt][2 * r] = v0; s[nt][2 * r + 1] = v1;
                mx = fmaxf(mx, fmaxf(v0, v1));
            }
            mx = fmaxf(mx, __shfl_xor_sync(0xffffffffu, mx, 1));
            mx = fmaxf(mx, __shfl_xor_sync(0xffffffffu, mx, 2));
            float nm = fmaxf(m[r], mx);
            float fac = __expf(m[r] - nm);
            m[r] = nm;
            float sum = 0.f;
#pragma unroll
            for (int nt = 0; nt < 8; nt++) {
                float e0 = __expf(s[nt][2 * r] - nm);
                float e1 = __expf(s[nt][2 * r + 1] - nm);
                sum += e0 + e1;
                *(__half2*)(Pb + (w16 + g + 8 * r) * AVSTR + (nt * 8 + 2 * t) * 2) =
                    __halves2half2(__float2half_rn(e0), __float2half_rn(e1));
            }
            sum += __shfl_xor_sync(0xffffffffu, sum, 1);
            sum += __shfl_xor_sync(0xffffffffu, sum, 2);
            l[r] = l[r] * fac + sum;
#pragma unroll
            for (int nt = 0; nt < 10; nt++) {
                o[nt][2 * r] *= fac;
                o[nt][2 * r + 1] *= fac;
            }
        }
        __syncwarp();

#pragma unroll
        for (int ks = 0; ks < 4; ks++) {
            uint32_t a[4];
            const char* pp = Pb + (w16 + g) * AVSTR + ks * 32 + 4 * t;
            a[0] = *(const uint32_t*)(pp);
            a[1] = *(const uint32_t*)(pp + 8 * AVSTR);
            a[2] = *(const uint32_t*)(pp + 16);
            a[3] = *(const uint32_t*)(pp + 8 * AVSTR + 16);
            uint32_t b[10][2];
#pragma unroll
            for (int nt = 0; nt < 10; nt++) {
                const char* vp = V + (nt * 8 + g) * AVSTR + ks * 32 + 4 * t;
                b[nt][0] = *(const uint32_t*)(vp);
                b[nt][1] = *(const uint32_t*)(vp + 16);
            }
#pragma unroll
            for (int nt = 0; nt < 10; nt++)
                mma_f16(o[nt], a, b[nt]);
        }
        __syncwarp();
    }

#pragma unroll
    for (int r = 0; r < 2; r++) {
        float inv = 1.f / l[r];
        const int row = q0 + w16 + g + 8 * r;
#pragma unroll
        for (int nt = 0; nt < 10; nt++) {
            *(__half2*)(out + (size_t)row * DMODEL + h * HDIM + nt * 8 + 2 * t) =
                __halves2half2(__float2half_rn(o[nt][2 * r] * inv),
                               __float2half_rn(o[nt][2 * r + 1] * inv));
        }
    }
}

// ---------------- launch ----------------
static void* sym_addr(const void* sym)
{
    void* p = nullptr;
    cudaGetSymbolAddress(&p, sym);
    return p;
}

extern "C" void kernel_launch(void* const* d_in, const int* in_sizes, int n_in,
                              void* d_out, int out_size)
{
    const float* x        = (const float*)d_in[0];
    const float* rot      = (const float*)d_in[1];
    const float* ln1_s    = (const float*)d_in[2];
    const float* ln1_b    = (const float*)d_in[3];
    const float* ln2_s    = (const float*)d_in[4];
    const float* ln2_b    = (const float*)d_in[5];
    const float* qkv_w    = (const float*)d_in[6];
    const float* qkv_b    = (const float*)d_in[7];
    const float* proj_w   = (const float*)d_in[8];
    const float* proj_b   = (const float*)d_in[9];
    const float* fc1_w    = (const float*)d_in[10];
    const float* fc1_b    = (const float*)d_in[11];
    const float* fc2_w    = (const float*)d_in[12];
    const float* fc2_b    = (const float*)d_in[13];
    const int*   cu       = (const int*)d_in[14];
    float*       out      = (float*)d_out;
    const int    nseg     = in_sizes[14] - 1;

    __half* hh    = (__half*)sym_addr(g_hh);
    __half* qkvh  = (__half*)sym_addr(g_qkvh);
    __half* qh    = (__half*)sym_addr(g_qh);
    __half* kh    = (__half*)sym_addr(g_kh);
    __half* vth   = (__half*)sym_addr(g_vth);
    __half* attnh = (__half*)sym_addr(g_attnh);
    float*  x1    = (float*)sym_addr(g_x1);
    __half* ffh   = (__half*)sym_addr(g_ffh);
    __half* whqkv = (__half*)sym_addr(g_wh_qkv);
    __half* whprj = (__half*)sym_addr(g_wh_proj);
    __half* whfc1 = (__half*)sym_addr(g_wh_fc1);
    __half* whfc2 = (__half*)sym_addr(g_wh_fc2);

    cudaFuncSetAttribute(attn_h_kernel, cudaFuncAttributeMaxDynamicSharedMemorySize, ATTN_SMEM_BYTES);
    const int gemm_smem = NSTAGE * STG_BYTES;  // 122880
    cudaFuncSetAttribute(gemm_h<0, 0, 1>, cudaFuncAttributeMaxDynamicSharedMemorySize, gemm_smem);
    cudaFuncSetAttribute(gemm_h<0, 1, 0>, cudaFuncAttributeMaxDynamicSharedMemorySize, gemm_smem);
    cudaFuncSetAttribute(gemm_h<1, 0, 1>, cudaFuncAttributeMaxDynamicSharedMemorySize, gemm_smem);

    // 0) weight transpose+convert to fp16 [N][K]
    transpose_h64<<<dim3(3 * DMODEL / 64, DMODEL / 64), 256>>>(qkv_w, whqkv, DMODEL, 3 * DMODEL);
    transpose_h64<<<dim3(DMODEL / 64, DMODEL / 64), 256>>>(proj_w, whprj, DMODEL, DMODEL);
    transpose_h64<<<dim3(FFDIM / 64, DMODEL / 64), 256>>>(fc1_w, whfc1, DMODEL, FFDIM);
    transpose_h64<<<dim3(DMODEL / 64, FFDIM / 64), 256>>>(fc2_w, whfc2, FFDIM, DMODEL);

    // 1) LN1 (fp16 output)
    ln_kernel<<<S_LEN, 256>>>(x, ln1_s, ln1_b, hh);
    // 2) QKV = h @ qkv_w + b  (fp16 out)
    gemm_h<0, 0, 1><<<dim3(3 * DMODEL / 256, S_LEN / 128), 256, gemm_smem>>>(
        hh, whqkv, qkv_b, nullptr, qkvh, S_LEN, 3 * DMODEL, DMODEL);
    // 3) RoPE -> fp16 q/k; V -> fp16 transposed
    {
        int total = S_LEN * 2 * NHEAD * 40;
        rope_h_kernel<<<(total + 255) / 256, 256>>>(qkvh, rot, qh, kh);
        vtrans_kernel<<<dim3(S_LEN / 64, NHEAD), 256>>>(qkvh, vth);
    }
    // 4) fp16 flash attention -> fp16
    attn_h_kernel<<<dim3(S_LEN / 64, NHEAD), 128, ATTN_SMEM_BYTES>>>(qh, kh, vth, cu, nseg, attnh);
    // 5) x1 = x + attn @ proj_w + proj_b  (fp32 out)
    gemm_h<0, 1, 0><<<dim3(DMODEL / 256, S_LEN / 128), 256, gemm_smem>>>(
        attnh, whprj, proj_b, x, x1, S_LEN, DMODEL, DMODEL);
    // 6) LN2 (fp16 output)
    ln_kernel<<<S_LEN, 256>>>(x1, ln2_s, ln2_b, hh);
    // 7) ff = quick_gelu(h @ fc1_w + fc1_b)  (fp16 out)
    gemm_h<1, 0, 1><<<dim3(FFDIM / 256, S_LEN / 128), 256, gemm_smem>>>(
        hh, whfc1, fc1_b, nullptr, ffh, S_LEN, FFDIM, DMODEL);
    // 8) out = x1 + ff @ fc2_w + fc2_b  (fp32 out)
    gemm_h<0, 1, 0><<<dim3(DMODEL / 256, S_LEN / 128), 256, gemm_smem>>>(
        ffh, whfc2, fc2_b, x1, out, S_LEN, DMODEL, FFDIM);
}

// round 15
// speedup vs baseline: 1.0280x; 1.0280x over previous
#include <cuda_runtime.h>
#include <cuda_fp16.h>
#include <math.h>
#include <stdint.h>

#define S_LEN 3072
#define DMODEL 1280
#define NHEAD 16
#define HDIM 80
#define FFDIM 5120

// ---------------- scratch (device globals; no allocations allowed) ----------
__device__ __half g_hh[S_LEN * DMODEL];        // LN output (fp16)
__device__ __half g_qkvh[S_LEN * 3 * DMODEL];  // QKV (fp16)
__device__ __half g_qh[S_LEN * DMODEL];        // rope'd Q (fp16)
__device__ __half g_kh[S_LEN * DMODEL];        // rope'd K (fp16)
__device__ __half g_vth[NHEAD * HDIM * S_LEN]; // V^T [h][d][s] (fp16)
__device__ __half g_attnh[S_LEN * DMODEL];     // attention output (fp16)
__device__ float  g_x1[S_LEN * DMODEL];        // x + proj(attn)  (fp32)
__device__ __half g_ffh[S_LEN * FFDIM];        // gelu(fc1) (fp16)
__device__ __half g_wh_qkv[3 * DMODEL * DMODEL];  // weights [N][K] fp16
__device__ __half g_wh_proj[DMODEL * DMODEL];
__device__ __half g_wh_fc1[FFDIM * DMODEL];
__device__ __half g_wh_fc2[DMODEL * FFDIM];

// ---------------- helpers ----------------
__device__ __forceinline__ uint32_t smem_u32(const void* p) {
    uint32_t a;
    asm("{ .reg .u64 t; cvta.to.shared.u64 t, %1; cvt.u32.u64 %0, t; }"
        : "=r"(a) : "l"(p));
    return a;
}

#define CP_ASYNC16(dst, src) \
    asm volatile("cp.async.cg.shared.global [%0], [%1], 16;" :: "r"(dst), "l"(src) : "memory")
#define CP_COMMIT() asm volatile("cp.async.commit_group;" ::: "memory")
#define CP_WAIT2()  asm volatile("cp.async.wait_group 2;" ::: "memory")
#define CP_WAIT0()  asm volatile("cp.async.wait_group 0;" ::: "memory")

// fp16 mma: D(f32) += A(f16 m16k16,row) * B(f16 k16n8,col)
__device__ __forceinline__ void mma_f16(float* c, const uint32_t* a, const uint32_t* b) {
    asm volatile(
        "mma.sync.aligned.m16n8k16.row.col.f32.f16.f16.f32 "
        "{%0,%1,%2,%3}, {%4,%5,%6,%7}, {%8,%9}, {%0,%1,%2,%3};"
        : "+f"(c[0]), "+f"(c[1]), "+f"(c[2]), "+f"(c[3])
        : "r"(a[0]), "r"(a[1]), "r"(a[2]), "r"(a[3]), "r"(b[0]), "r"(b[1]));
}

// ---------------- weight transpose + fp16 convert: in[K,N] -> out[N,K] ----
__global__ __launch_bounds__(256) void transpose_h64(
    const float* __restrict__ in, __half* __restrict__ out, int K, int N)
{
    __shared__ float t[64][65];
    int n0 = blockIdx.x * 64, k0 = blockIdx.y * 64;
    int tid = threadIdx.x;
#pragma unroll
    for (int it = 0; it < 16; it++) {
        int idx = tid + it * 256;
        int r = idx >> 6, c = idx & 63;
        t[r][c] = in[(size_t)(k0 + r) * N + n0 + c];
    }
    __syncthreads();
#pragma unroll
    for (int it = 0; it < 16; it++) {
        int idx = tid + it * 256;
        int j = idx >> 6, i = idx & 63;
        out[(size_t)(n0 + j) * K + k0 + i] = __float2half_rn(t[i][j]);
    }
}

// ---------------- fp16 mma GEMM: C = A[M,K] @ Bt[N,K]^T + bias ------------
// BM=128, BN=256, BK=32, 4 stages, 256 threads (8 warps 2x4), warp tile 64x64.
// Scalar fragment loads (R13-proven; ldmatrix variant regressed).
#define RSTR 80                       // smem row stride, bytes
#define A_BYTES (128 * RSTR)          // 10240
#define B_BYTES (256 * RSTR)          // 20480
#define STG_BYTES (A_BYTES + B_BYTES) // 30720
#define NSTAGE 4

template <int ACT, int RES, int OUTH>
__global__ __launch_bounds__(256, 1)
void gemm_h(const __half* __restrict__ A, const __half* __restrict__ Bt,
            const float* __restrict__ bias, const float* __restrict__ res,
            void* __restrict__ Cv, int M, int N, int K)
{
    extern __shared__ __align__(16) char smem[];
    const uint32_t sb = smem_u32(smem);
    const int tid = threadIdx.x;
    const int wid = tid >> 5, lane = tid & 31;
    const int g = lane >> 2, t = lane & 3;
    const int warp_m = (wid >> 2) * 64;
    const int warp_n = (wid & 3) * 64;
    const int m0 = blockIdx.y * 128;
    const int n0 = blockIdx.x * 256;
    const int nk = K / 32;

    float c[4][8][4];
#pragma unroll
    for (int mt = 0; mt < 4; mt++)
#pragma unroll
        for (int nt = 0; nt < 8; nt++)
#pragma unroll
            for (int i = 0; i < 4; i++) c[mt][nt][i] = 0.f;

    auto load_tile = [&](int stage, int k0) {
        uint32_t sA = sb + (uint32_t)stage * STG_BYTES;
        uint32_t sB = sA + A_BYTES;
#pragma unroll
        for (int cc = 0; cc < 2; cc++) {
            int idx = tid + cc * 256;
            int row = idx >> 2, off = idx & 3;
            CP_ASYNC16(sA + (uint32_t)row * RSTR + (uint32_t)off * 16,
                       (const char*)(A + (size_t)(m0 + row) * K + k0) + off * 16);
        }
#pragma unroll
        for (int cc = 0; cc < 4; cc++) {
            int idx = tid + cc * 256;
            int row = idx >> 2, off = idx & 3;
            CP_ASYNC16(sB + (uint32_t)row * RSTR + (uint32_t)off * 16,
                       (const char*)(Bt + (size_t)(n0 + row) * K + k0) + off * 16);
        }
    };

    int k0 = 0;
#pragma unroll
    for (int s = 0; s < NSTAGE - 1; s++) {
        load_tile(s, k0);
        CP_COMMIT();
        k0 += 32;
    }

    for (int it = 0; it < nk; it++) {
        CP_WAIT2();
        __syncthreads();
        const int cur = it & (NSTAGE - 1);
        if (k0 < K) {
            load_tile((it + NSTAGE - 1) & (NSTAGE - 1), k0);
            k0 += 32;
        }
        CP_COMMIT();

        const char* As = smem + (size_t)cur * STG_BYTES;
        const char* Bs = As + A_BYTES;

#pragma unroll
        for (int kk = 0; kk < 2; kk++) {
            const int kb = kk * 32;
            uint32_t a[4][4], b[8][2];
#pragma unroll
            for (int mt = 0; mt < 4; mt++) {
                const char* ap = As + (warp_m + mt * 16 + g) * RSTR + kb + 4 * t;
                a[mt][0] = *(const uint32_t*)(ap);
                a[mt][1] = *(const uint32_t*)(ap + 8 * RSTR);
                a[mt][2] = *(const uint32_t*)(ap + 16);
                a[mt][3] = *(const uint32_t*)(ap + 8 * RSTR + 16);
            }
#pragma unroll
            for (int nt = 0; nt < 8; nt++) {
                const char* bp = Bs + (warp_n + nt * 8 + g) * RSTR + kb + 4 * t;
                b[nt][0] = *(const uint32_t*)(bp);
                b[nt][1] = *(const uint32_t*)(bp + 16);
            }
#pragma unroll
            for (int mt = 0; mt < 4; mt++)
#pragma unroll
                for (int nt = 0; nt < 8; nt++)
                    mma_f16(c[mt][nt], a[mt], b[nt]);
        }
    }

#pragma unroll
    for (int mt = 0; mt < 4; mt++) {
        const int rm = m0 + warp_m + mt * 16 + g;
#pragma unroll
        for (int nt = 0; nt < 8; nt++) {
            const int cn = n0 + warp_n + nt * 8 + 2 * t;
            float2 bv = *(const float2*)(bias + cn);
            float v0 = c[mt][nt][0] + bv.x;
            float v1 = c[mt][nt][1] + bv.y;
            float v2 = c[mt][nt][2] + bv.x;
            float v3 = c[mt][nt][3] + bv.y;
            if (RES) {
                float2 r0 = *(const float2*)(res + (size_t)rm * N + cn);
                float2 r1 = *(const float2*)(res + (size_t)(rm + 8) * N + cn);
                v0 += r0.x; v1 += r0.y; v2 += r1.x; v3 += r1.y;
            }
            if (ACT) {
                v0 = v0 / (1.f + __expf(-1.702f * v0));
                v1 = v1 / (1.f + __expf(-1.702f * v1));
                v2 = v2 / (1.f + __expf(-1.702f * v2));
                v3 = v3 / (1.f + __expf(-1.702f * v3));
            }
            if (OUTH) {
                __half* C = (__half*)Cv;
                *(__half2*)(C + (size_t)rm * N + cn) =
                    __halves2half2(__float2half_rn(v0), __float2half_rn(v1));
                *(__half2*)(C + (size_t)(rm + 8) * N + cn) =
                    __halves2half2(__float2half_rn(v2), __float2half_rn(v3));
            } else {
                float* C = (float*)Cv;
                *(float2*)(C + (size_t)rm * N + cn)       = make_float2(v0, v1);
                *(float2*)(C + (size_t)(rm + 8) * N + cn) = make_float2(v2, v3);
            }
        }
    }
}

// ---------------- LayerNorm (fp16 output) ----------------
__global__ __launch_bounds__(256) void ln_kernel(
    const float* __restrict__ x, const float* __restrict__ sc,
    const float* __restrict__ bi, __half* __restrict__ out)
{
    int row = blockIdx.x;
    const float* xr = x + row * DMODEL;
    __half* orow = out + (size_t)row * DMODEL;
    int t = threadIdx.x;
    float v[5];
    float s = 0.f, s2 = 0.f;
#pragma unroll
    for (int i = 0; i < 5; i++) {
        v[i] = xr[t + i * 256];
        s += v[i];
        s2 = fmaf(v[i], v[i], s2);
    }
    __shared__ float rs[8], rs2[8];
#pragma unroll
    for (int o = 16; o; o >>= 1) {
        s  += __shfl_xor_sync(0xffffffffu, s, o);
        s2 += __shfl_xor_sync(0xffffffffu, s2, o);
    }
    if ((t & 31) == 0) { rs[t >> 5] = s; rs2[t >> 5] = s2; }
    __syncthreads();
    if (t < 32) {
        float a = (t < 8) ? rs[t] : 0.f;
        float b = (t < 8) ? rs2[t] : 0.f;
#pragma unroll
        for (int o = 4; o; o >>= 1) {
            a += __shfl_xor_sync(0xffffffffu, a, o);
            b += __shfl_xor_sync(0xffffffffu, b, o);
        }
        if (t == 0) { rs[0] = a; rs2[0] = b; }
    }
    __syncthreads();
    float mu = rs[0] * (1.f / DMODEL);
    float var = rs2[0] * (1.f / DMODEL) - mu * mu;
    float inv = rsqrtf(var + 1e-6f);
#pragma unroll
    for (int i = 0; i < 5; i++) {
        int c = t + i * 256;
        orow[c] = __float2half_rn((v[i] - mu) * inv * sc[c] + bi[c]);
    }
}

// ---------------- RoPE: q,k fp16 -> rotated fp16 buffers ----------------
__global__ __launch_bounds__(256) void rope_h_kernel(
    const __half* __restrict__ qkv, const float* __restrict__ rot,
    __half* __restrict__ qh, __half* __restrict__ kh)
{
    int idx = blockIdx.x * 256 + threadIdx.x;
    const int total = S_LEN * 2 * NHEAD * 40;
    if (idx >= total) return;
    int i = idx % 40;
    int h = (idx / 40) % NHEAD;
    int w = (idx / (40 * NHEAD)) % 2;
    int s = idx / (40 * NHEAD * 2);
    const __half* p = qkv + (size_t)s * (3 * DMODEL) + w * DMODEL + h * HDIM;
    __half* dst = (w == 0 ? qh : kh) + (size_t)s * DMODEL + h * HDIM;
    float x1 = __half2float(p[i]);
    float x2 = __half2float(p[i + 40]);
    float f1 = rot[s * 40 + (i >> 1)];
    float f2 = rot[s * 40 + 20 + (i >> 1)];
    float c1, s1, c2, s2v;
    sincosf(f1, &s1, &c1);
    sincosf(f2, &s2v, &c2);
    dst[i]      = __float2half_rn(x1 * c1 - x2 * s1);
    dst[i + 40] = __float2half_rn(x2 * c2 + x1 * s2v);
}

// ---------------- V transpose: qkv fp16 [s][v:h*80+d] -> vth fp16 [h][d][s]
__global__ __launch_bounds__(256) void vtrans_kernel(
    const __half* __restrict__ qkv, __half* __restrict__ vth)
{
    __shared__ float t[HDIM][65];
    int s0 = blockIdx.x * 64;
    int h = blockIdx.y;
    int tid = threadIdx.x;
#pragma unroll
    for (int it = 0; it < 20; it++) {
        int idx = tid + it * 256;
        int sl = idx / 80, d = idx % 80;
        t[d][sl] = __half2float(
            qkv[(size_t)(s0 + sl) * (3 * DMODEL) + 2 * DMODEL + h * HDIM + d]);
    }
    __syncthreads();
#pragma unroll
    for (int it = 0; it < 20; it++) {
        int idx = tid + it * 256;
        int d = idx >> 6, sl = idx & 63;
        vth[(size_t)(h * HDIM + d) * S_LEN + s0 + sl] = __float2half_rn(t[d][sl]);
    }
}

// ---------------- fp16 flash attention (block-diag segments) --------------
#define AQSTR 176   // Q/K smem row stride, bytes
#define AVSTR 144   // VT & P smem row stride, bytes
#define AOFF_Q  0
#define AOFF_K0 11264
#define AOFF_K1 22528
#define AOFF_V0 33792
#define AOFF_V1 45312
#define ATTN_SMEM_BYTES 56832

__global__ __launch_bounds__(128, 1) void attn_h_kernel(
    const __half* __restrict__ qh, const __half* __restrict__ kh,
    const __half* __restrict__ vth, const int* __restrict__ cu,
    int nseg, __half* __restrict__ out)
{
    extern __shared__ __align__(16) char sm[];
    const uint32_t sb = smem_u32(sm);
    const int tid = threadIdx.x;
    const int warp = tid >> 5, lane = tid & 31;
    const int g = lane >> 2, t = lane & 3;
    const int h = blockIdx.y;
    const int q0 = blockIdx.x * 64;
    const int w16 = warp * 16;

    int start = 0, end = S_LEN;
    for (int i = 0; i < nseg; i++) {
        int a = cu[i], b = cu[i + 1];
        if (q0 >= a && q0 < b) { start = a; end = b; break; }
    }
    const int L = end - start;
    const int ntiles = (L + 63) >> 6;

    for (int i = tid; i < 640; i += 128) {
        int row = i / 10, c = i % 10;
        CP_ASYNC16(sb + AOFF_Q + (uint32_t)row * AQSTR + (uint32_t)c * 16,
                   (const char*)(qh + (size_t)(q0 + row) * DMODEL + h * HDIM) + c * 16);
    }
    CP_COMMIT();

    auto load_kv = [&](int stage, int k0) {
        const uint32_t kBase = sb + (stage ? AOFF_K1 : AOFF_K0);
        const uint32_t vBase = sb + (stage ? AOFF_V1 : AOFF_V0);
        for (int i = tid; i < 640; i += 128) {
            int row = i / 10, c = i % 10;
            int key = k0 + row;
            int src = start + (key < L ? key : L - 1);
            CP_ASYNC16(kBase + (uint32_t)row * AQSTR + (uint32_t)c * 16,
                       (const char*)(kh + (size_t)src * DMODEL + h * HDIM) + c * 16);
        }
        for (int i = tid; i < 640; i += 128) {
            int d = i >> 3, c = i & 7;
            int kk0 = k0 + c * 8;
            if (kk0 + 8 > L) kk0 = L - 8;
            CP_ASYNC16(vBase + (uint32_t)d * AVSTR + (uint32_t)c * 16,
                       (const char*)(vth + (size_t)(h * HDIM + d) * S_LEN + start + kk0));
        }
    };

    load_kv(0, 0);
    CP_COMMIT();
    CP_WAIT0();
    __syncthreads();

    uint32_t qf[5][4];
#pragma unroll
    for (int ks = 0; ks < 5; ks++) {
        const char* qp = sm + AOFF_Q + (w16 + g) * AQSTR + ks * 32 + 4 * t;
        qf[ks][0] = *(const uint32_t*)(qp);
        qf[ks][1] = *(const uint32_t*)(qp + 8 * AQSTR);
        qf[ks][2] = *(const uint32_t*)(qp + 16);
        qf[ks][3] = *(const uint32_t*)(qp + 8 * AQSTR + 16);
    }
    __syncthreads();

    if (1 < ntiles) {
        load_kv(1, 64);
    }
    CP_COMMIT();

    const float scale = 0.111803398875f;   // 1/sqrt(80)
    float m[2] = {-1e30f, -1e30f};
    float l[2] = {0.f, 0.f};
    float o[10][4];
#pragma unroll
    for (int nt = 0; nt < 10; nt++)
#pragma unroll
        for (int i = 0; i < 4; i++) o[nt][i] = 0.f;

    char* Pb = sm + AOFF_Q;

    for (int kt = 0; kt < ntiles; kt++) {
        if (kt > 0) {
            CP_WAIT0();
            __syncthreads();
            if (kt + 1 < ntiles) {
                load_kv((kt + 1) & 1, (kt + 1) * 64);
            }
            CP_COMMIT();
        }
        const char* K = sm + ((kt & 1) ? AOFF_K1 : AOFF_K0);
        const char* V = sm + ((kt & 1) ? AOFF_V1 : AOFF_V0);

        float s[8][4];
#pragma unroll
        for (int nt = 0; nt < 8; nt++)
#pragma unroll
            for (int i = 0; i < 4; i++) s[nt][i] = 0.f;
#pragma unroll
        for (int ks = 0; ks < 5; ks++) {
            uint32_t b[8][2];
#pragma unroll
            for (int nt = 0; nt < 8; nt++) {
                const char* kp = K + (nt * 8 + g) * AQSTR + ks * 32 + 4 * t;
                b[nt][0] = *(const uint32_t*)(kp);
                b[nt][1] = *(const uint32_t*)(kp + 16);
            }
#pragma unroll
            for (int nt = 0; nt < 8; nt++)
                mma_f16(s[nt], qf[ks], b[nt]);
        }

        const bool maskT = (kt == ntiles - 1) && (L & 63);
#pragma unroll
        for (int r = 0; r < 2; r++) {
            float mx = -1e30f;
#pragma unroll
            for (int nt = 0; nt < 8; nt++) {
                float v0 = s[nt][2 * r]     * scale;
                float v1 = s[nt][2 * r + 1] * scale;
                if (maskT) {
                    int col = kt * 64 + nt * 8 + 2 * t;
                    if (col >= L)     v0 = -1e30f;
                    if (col + 1 >= L) v1 = -1e30f;
                }
                s[nt][2 * r] = v0; s[nt][2 * r + 1] = v1;
                mx = fmaxf(mx, fmaxf(v0, v1));
            }
            mx = fmaxf(mx, __shfl_xor_sync(0xffffffffu, mx, 1));
            mx = fmaxf(mx, __shfl_xor_sync(0xffffffffu, mx, 2));
            float nm = fmaxf(m[r], mx);
            float fac = __expf(m[r] - nm);
            m[r] = nm;
            float sum = 0.f;
#pragma unroll
            for (int nt = 0; nt < 8; nt++) {
                float e0 = __expf(s[nt][2 * r] - nm);
                float e1 = __expf(s[nt][2 * r + 1] - nm);
                sum += e0 + e1;
                *(__half2*)(Pb + (w16 + g + 8 * r) * AVSTR + (nt * 8 + 2 * t) * 2) =
                    __halves2half2(__float2half_rn(e0), __float2half_rn(e1));
            }
            sum += __shfl_xor_sync(0xffffffffu, sum, 1);
            sum += __shfl_xor_sync(0xffffffffu, sum, 2);
            l[r] = l[r] * fac + sum;
#pragma unroll
            for (int nt = 0; nt < 10; nt++) {
                o[nt][2 * r] *= fac;
                o[nt][2 * r + 1] *= fac;
            }
        }
        __syncwarp();

#pragma unroll
        for (int ks = 0; ks < 4; ks++) {
            uint32_t a[4];
            const char* pp = Pb + (w16 + g) * AVSTR + ks * 32 + 4 * t;
            a[0] = *(const uint32_t*)(pp);
            a[1] = *(const uint32_t*)(pp + 8 * AVSTR);
            a[2] = *(const uint32_t*)(pp + 16);
            a[3] = *(const uint32_t*)(pp + 8 * AVSTR + 16);
            uint32_t b[10][2];
#pragma unroll
            for (int nt = 0; nt < 10; nt++) {
                const char* vp = V + (nt * 8 + g) * AVSTR + ks * 32 + 4 * t;
                b[nt][0] = *(const uint32_t*)(vp);
                b[nt][1] = *(const uint32_t*)(vp + 16);
            }
#pragma unroll
            for (int nt = 0; nt < 10; nt++)
                mma_f16(o[nt], a, b[nt]);
        }
        __syncwarp();
    }

#pragma unroll
    for (int r = 0; r < 2; r++) {
        float inv = 1.f / l[r];
        const int row = q0 + w16 + g + 8 * r;
#pragma unroll
        for (int nt = 0; nt < 10; nt++) {
            *(__half2*)(out + (size_t)row * DMODEL + h * HDIM + nt * 8 + 2 * t) =
                __halves2half2(__float2half_rn(o[nt][2 * r] * inv),
                               __float2half_rn(o[nt][2 * r + 1] * inv));
        }
    }
}

// ---------------- launch ----------------
static void* sym_addr(const void* sym)
{
    void* p = nullptr;
    cudaGetSymbolAddress(&p, sym);
    return p;
}

extern "C" void kernel_launch(void* const* d_in, const int* in_sizes, int n_in,
                              void* d_out, int out_size)
{
    const float* x        = (const float*)d_in[0];
    const float* rot      = (const float*)d_in[1];
    const float* ln1_s    = (const float*)d_in[2];
    const float* ln1_b    = (const float*)d_in[3];
    const float* ln2_s    = (const float*)d_in[4];
    const float* ln2_b    = (const float*)d_in[5];
    const float* qkv_w    = (const float*)d_in[6];
    const float* qkv_b    = (const float*)d_in[7];
    const float* proj_w   = (const float*)d_in[8];
    const float* proj_b   = (const float*)d_in[9];
    const float* fc1_w    = (const float*)d_in[10];
    const float* fc1_b    = (const float*)d_in[11];
    const float* fc2_w    = (const float*)d_in[12];
    const float* fc2_b    = (const float*)d_in[13];
    const int*   cu       = (const int*)d_in[14];
    float*       out      = (float*)d_out;
    const int    nseg     = in_sizes[14] - 1;

    __half* hh    = (__half*)sym_addr(g_hh);
    __half* qkvh  = (__half*)sym_addr(g_qkvh);
    __half* qh    = (__half*)sym_addr(g_qh);
    __half* kh    = (__half*)sym_addr(g_kh);
    __half* vth   = (__half*)sym_addr(g_vth);
    __half* attnh = (__half*)sym_addr(g_attnh);
    float*  x1    = (float*)sym_addr(g_x1);
    __half* ffh   = (__half*)sym_addr(g_ffh);
    __half* whqkv = (__half*)sym_addr(g_wh_qkv);
    __half* whprj = (__half*)sym_addr(g_wh_proj);
    __half* whfc1 = (__half*)sym_addr(g_wh_fc1);
    __half* whfc2 = (__half*)sym_addr(g_wh_fc2);

    cudaFuncSetAttribute(attn_h_kernel, cudaFuncAttributeMaxDynamicSharedMemorySize, ATTN_SMEM_BYTES);
    const int gemm_smem = NSTAGE * STG_BYTES;  // 122880
    cudaFuncSetAttribute(gemm_h<0, 0, 1>, cudaFuncAttributeMaxDynamicSharedMemorySize, gemm_smem);
    cudaFuncSetAttribute(gemm_h<0, 1, 0>, cudaFuncAttributeMaxDynamicSharedMemorySize, gemm_smem);
    cudaFuncSetAttribute(gemm_h<1, 0, 1>, cudaFuncAttributeMaxDynamicSharedMemorySize, gemm_smem);

    // 0) weight transpose+convert to fp16 [N][K]
    transpose_h64<<<dim3(3 * DMODEL / 64, DMODEL / 64), 256>>>(qkv_w, whqkv, DMODEL, 3 * DMODEL);
    transpose_h64<<<dim3(DMODEL / 64, DMODEL / 64), 256>>>(proj_w, whprj, DMODEL, DMODEL);
    transpose_h64<<<dim3(FFDIM / 64, DMODEL / 64), 256>>>(fc1_w, whfc1, DMODEL, FFDIM);
    transpose_h64<<<dim3(DMODEL / 64, FFDIM / 64), 256>>>(fc2_w, whfc2, FFDIM, DMODEL);

    // 1) LN1 (fp16 output)
    ln_kernel<<<S_LEN, 256>>>(x, ln1_s, ln1_b, hh);
    // 2) QKV = h @ qkv_w + b  (fp16 out)
    gemm_h<0, 0, 1><<<dim3(3 * DMODEL / 256, S_LEN / 128), 256, gemm_smem>>>(
        hh, whqkv, qkv_b, nullptr, qkvh, S_LEN, 3 * DMODEL, DMODEL);
    // 3) RoPE -> fp16 q/k; V -> fp16 transposed
    {
        int total = S_LEN * 2 * NHEAD * 40;
        rope_h_kernel<<<(total + 255) / 256, 256>>>(qkvh, rot, qh, kh);
        vtrans_kernel<<<dim3(S_LEN / 64, NHEAD), 256>>>(qkvh, vth);
    }
    // 4) fp16 flash attention -> fp16
    attn_h_kernel<<<dim3(S_LEN / 64, NHEAD), 128, ATTN_SMEM_BYTES>>>(qh, kh, vth, cu, nseg, attnh);
    // 5) x1 = x + attn @ proj_w + proj_b  (fp32 out)
    gemm_h<0, 1, 0><<<dim3(DMODEL / 256, S_LEN / 128), 256, gemm_smem>>>(
        attnh, whprj, proj_b, x, x1, S_LEN, DMODEL, DMODEL);
    // 6) LN2 (fp16 output)
    ln_kernel<<<S_LEN, 256>>>(x1, ln2_s, ln2_b, hh);
    // 7) ff = quick_gelu(h @ fc1_w + fc1_b)  (fp16 out)
    gemm_h<1, 0, 1><<<dim3(FFDIM / 256, S_LEN / 128), 256, gemm_smem>>>(
        hh, whfc1, fc1_b, nullptr, ffh, S_LEN, FFDIM, DMODEL);
    // 8) out = x1 + ff @ fc2_w + fc2_b  (fp32 out)
    gemm_h<0, 1, 0><<<dim3(DMODEL / 256, S_LEN / 128), 256, gemm_smem>>>(
        ffh, whfc2, fc2_b, x1, out, S_LEN, DMODEL, FFDIM);
}

// round 16
// speedup vs baseline: 1.1035x; 1.0735x over previous
#include <cuda_runtime.h>
#include <cuda_fp16.h>
#include <math.h>
#include <stdint.h>

#define S_LEN 3072
#define DMODEL 1280
#define NHEAD 16
#define HDIM 80
#define FFDIM 5120

// ---------------- scratch (device globals; no allocations allowed) ----------
__device__ __half g_hh[S_LEN * DMODEL];        // LN output (fp16)
__device__ __half g_qkvh[S_LEN * 3 * DMODEL];  // QKV (fp16)
__device__ __half g_qh[S_LEN * DMODEL];        // rope'd Q (fp16)
__device__ __half g_kh[S_LEN * DMODEL];        // rope'd K (fp16)
__device__ __half g_vth[NHEAD * HDIM * S_LEN]; // V^T [h][d][s] (fp16)
__device__ __half g_attnh[S_LEN * DMODEL];     // attention output (fp16)
__device__ float  g_x1[S_LEN * DMODEL];        // x + proj(attn)  (fp32)
__device__ __half g_ffh[S_LEN * FFDIM];        // gelu(fc1) (fp16)
__device__ __half g_wh_qkv[3 * DMODEL * DMODEL];  // weights [N][K] fp16
__device__ __half g_wh_proj[DMODEL * DMODEL];
__device__ __half g_wh_fc1[FFDIM * DMODEL];
__device__ __half g_wh_fc2[DMODEL * FFDIM];

// ---------------- helpers ----------------
__device__ __forceinline__ uint32_t smem_u32(const void* p) {
    uint32_t a;
    asm("{ .reg .u64 t; cvta.to.shared.u64 t, %1; cvt.u32.u64 %0, t; }"
        : "=r"(a) : "l"(p));
    return a;
}

#define CP_ASYNC16(dst, src) \
    asm volatile("cp.async.cg.shared.global [%0], [%1], 16;" :: "r"(dst), "l"(src) : "memory")
#define CP_COMMIT() asm volatile("cp.async.commit_group;" ::: "memory")
#define CP_WAIT2()  asm volatile("cp.async.wait_group 2;" ::: "memory")
#define CP_WAIT0()  asm volatile("cp.async.wait_group 0;" ::: "memory")

// fp16 mma: D(f32) += A(f16 m16k16,row) * B(f16 k16n8,col)
__device__ __forceinline__ void mma_f16(float* c, const uint32_t* a, const uint32_t* b) {
    asm volatile(
        "mma.sync.aligned.m16n8k16.row.col.f32.f16.f16.f32 "
        "{%0,%1,%2,%3}, {%4,%5,%6,%7}, {%8,%9}, {%0,%1,%2,%3};"
        : "+f"(c[0]), "+f"(c[1]), "+f"(c[2]), "+f"(c[3])
        : "r"(a[0]), "r"(a[1]), "r"(a[2]), "r"(a[3]), "r"(b[0]), "r"(b[1]));
}

// ---------------- weight transpose + fp16 convert: in[K,N] -> out[N,K] ----
__global__ __launch_bounds__(256) void transpose_h64(
    const float* __restrict__ in, __half* __restrict__ out, int K, int N)
{
    __shared__ float t[64][65];
    int n0 = blockIdx.x * 64, k0 = blockIdx.y * 64;
    int tid = threadIdx.x;
#pragma unroll
    for (int it = 0; it < 16; it++) {
        int idx = tid + it * 256;
        int r = idx >> 6, c = idx & 63;
        t[r][c] = in[(size_t)(k0 + r) * N + n0 + c];
    }
    __syncthreads();
#pragma unroll
    for (int it = 0; it < 16; it++) {
        int idx = tid + it * 256;
        int j = idx >> 6, i = idx & 63;
        out[(size_t)(n0 + j) * K + k0 + i] = __float2half_rn(t[i][j]);
    }
}

// ---------------- fp16 mma GEMM: C = A[M,K] @ Bt[N,K]^T + bias ------------
// BM=128, BN=128, BK=32, 4 stages, 256 threads (8 warps 2x4), warp tile 64x32.
// Occupancy 2 (81920B smem/CTA) -> finer wave granularity, less tail waste.
#define RSTR 80                       // smem row stride, bytes
#define A_BYTES (128 * RSTR)          // 10240
#define B_BYTES (128 * RSTR)          // 10240
#define STG_BYTES (A_BYTES + B_BYTES) // 20480
#define NSTAGE 4

template <int ACT, int RES, int OUTH>
__global__ __launch_bounds__(256, 2)
void gemm_h(const __half* __restrict__ A, const __half* __restrict__ Bt,
            const float* __restrict__ bias, const float* __restrict__ res,
            void* __restrict__ Cv, int M, int N, int K)
{
    extern __shared__ __align__(16) char smem[];
    const uint32_t sb = smem_u32(smem);
    const int tid = threadIdx.x;
    const int wid = tid >> 5, lane = tid & 31;
    const int g = lane >> 2, t = lane & 3;
    const int warp_m = (wid >> 2) * 64;   // 0 or 64
    const int warp_n = (wid & 3) * 32;    // 0,32,64,96
    const int m0 = blockIdx.y * 128;
    const int n0 = blockIdx.x * 128;
    const int nk = K / 32;

    float c[4][4][4];
#pragma unroll
    for (int mt = 0; mt < 4; mt++)
#pragma unroll
        for (int nt = 0; nt < 4; nt++)
#pragma unroll
            for (int i = 0; i < 4; i++) c[mt][nt][i] = 0.f;

    auto load_tile = [&](int stage, int k0) {
        uint32_t sA = sb + (uint32_t)stage * STG_BYTES;
        uint32_t sB = sA + A_BYTES;
#pragma unroll
        for (int cc = 0; cc < 2; cc++) {           // A: 128 rows x 4 chunks
            int idx = tid + cc * 256;
            int row = idx >> 2, off = idx & 3;
            CP_ASYNC16(sA + (uint32_t)row * RSTR + (uint32_t)off * 16,
                       (const char*)(A + (size_t)(m0 + row) * K + k0) + off * 16);
        }
#pragma unroll
        for (int cc = 0; cc < 2; cc++) {           // B: 128 rows x 4 chunks
            int idx = tid + cc * 256;
            int row = idx >> 2, off = idx & 3;
            CP_ASYNC16(sB + (uint32_t)row * RSTR + (uint32_t)off * 16,
                       (const char*)(Bt + (size_t)(n0 + row) * K + k0) + off * 16);
        }
    };

    int k0 = 0;
#pragma unroll
    for (int s = 0; s < NSTAGE - 1; s++) {
        load_tile(s, k0);
        CP_COMMIT();
        k0 += 32;
    }

    for (int it = 0; it < nk; it++) {
        CP_WAIT2();
        __syncthreads();
        const int cur = it & (NSTAGE - 1);
        if (k0 < K) {
            load_tile((it + NSTAGE - 1) & (NSTAGE - 1), k0);
            k0 += 32;
        }
        CP_COMMIT();

        const char* As = smem + (size_t)cur * STG_BYTES;
        const char* Bs = As + A_BYTES;

#pragma unroll
        for (int kk = 0; kk < 2; kk++) {
            const int kb = kk * 32;
            uint32_t a[4][4], b[4][2];
#pragma unroll
            for (int mt = 0; mt < 4; mt++) {
                const char* ap = As + (warp_m + mt * 16 + g) * RSTR + kb + 4 * t;
                a[mt][0] = *(const uint32_t*)(ap);
                a[mt][1] = *(const uint32_t*)(ap + 8 * RSTR);
                a[mt][2] = *(const uint32_t*)(ap + 16);
                a[mt][3] = *(const uint32_t*)(ap + 8 * RSTR + 16);
            }
#pragma unroll
            for (int nt = 0; nt < 4; nt++) {
                const char* bp = Bs + (warp_n + nt * 8 + g) * RSTR + kb + 4 * t;
                b[nt][0] = *(const uint32_t*)(bp);
                b[nt][1] = *(const uint32_t*)(bp + 16);
            }
#pragma unroll
            for (int mt = 0; mt < 4; mt++)
#pragma unroll
                for (int nt = 0; nt < 4; nt++)
                    mma_f16(c[mt][nt], a[mt], b[nt]);
        }
    }

#pragma unroll
    for (int mt = 0; mt < 4; mt++) {
        const int rm = m0 + warp_m + mt * 16 + g;
#pragma unroll
        for (int nt = 0; nt < 4; nt++) {
            const int cn = n0 + warp_n + nt * 8 + 2 * t;
            float2 bv = *(const float2*)(bias + cn);
            float v0 = c[mt][nt][0] + bv.x;
            float v1 = c[mt][nt][1] + bv.y;
            float v2 = c[mt][nt][2] + bv.x;
            float v3 = c[mt][nt][3] + bv.y;
            if (RES) {
                float2 r0 = *(const float2*)(res + (size_t)rm * N + cn);
                float2 r1 = *(const float2*)(res + (size_t)(rm + 8) * N + cn);
                v0 += r0.x; v1 += r0.y; v2 += r1.x; v3 += r1.y;
            }
            if (ACT) {
                v0 = v0 / (1.f + __expf(-1.702f * v0));
                v1 = v1 / (1.f + __expf(-1.702f * v1));
                v2 = v2 / (1.f + __expf(-1.702f * v2));
                v3 = v3 / (1.f + __expf(-1.702f * v3));
            }
            if (OUTH) {
                __half* C = (__half*)Cv;
                *(__half2*)(C + (size_t)rm * N + cn) =
                    __halves2half2(__float2half_rn(v0), __float2half_rn(v1));
                *(__half2*)(C + (size_t)(rm + 8) * N + cn) =
                    __halves2half2(__float2half_rn(v2), __float2half_rn(v3));
            } else {
                float* C = (float*)Cv;
                *(float2*)(C + (size_t)rm * N + cn)       = make_float2(v0, v1);
                *(float2*)(C + (size_t)(rm + 8) * N + cn) = make_float2(v2, v3);
            }
        }
    }
}

// ---------------- LayerNorm (fp16 output) ----------------
__global__ __launch_bounds__(256) void ln_kernel(
    const float* __restrict__ x, const float* __restrict__ sc,
    const float* __restrict__ bi, __half* __restrict__ out)
{
    int row = blockIdx.x;
    const float* xr = x + row * DMODEL;
    __half* orow = out + (size_t)row * DMODEL;
    int t = threadIdx.x;
    float v[5];
    float s = 0.f, s2 = 0.f;
#pragma unroll
    for (int i = 0; i < 5; i++) {
        v[i] = xr[t + i * 256];
        s += v[i];
        s2 = fmaf(v[i], v[i], s2);
    }
    __shared__ float rs[8], rs2[8];
#pragma unroll
    for (int o = 16; o; o >>= 1) {
        s  += __shfl_xor_sync(0xffffffffu, s, o);
        s2 += __shfl_xor_sync(0xffffffffu, s2, o);
    }
    if ((t & 31) == 0) { rs[t >> 5] = s; rs2[t >> 5] = s2; }
    __syncthreads();
    if (t < 32) {
        float a = (t < 8) ? rs[t] : 0.f;
        float b = (t < 8) ? rs2[t] : 0.f;
#pragma unroll
        for (int o = 4; o; o >>= 1) {
            a += __shfl_xor_sync(0xffffffffu, a, o);
            b += __shfl_xor_sync(0xffffffffu, b, o);
        }
        if (t == 0) { rs[0] = a; rs2[0] = b; }
    }
    __syncthreads();
    float mu = rs[0] * (1.f / DMODEL);
    float var = rs2[0] * (1.f / DMODEL) - mu * mu;
    float inv = rsqrtf(var + 1e-6f);
#pragma unroll
    for (int i = 0; i < 5; i++) {
        int c = t + i * 256;
        orow[c] = __float2half_rn((v[i] - mu) * inv * sc[c] + bi[c]);
    }
}

// ---------------- RoPE: q,k fp16 -> rotated fp16 buffers ----------------
__global__ __launch_bounds__(256) void rope_h_kernel(
    const __half* __restrict__ qkv, const float* __restrict__ rot,
    __half* __restrict__ qh, __half* __restrict__ kh)
{
    int idx = blockIdx.x * 256 + threadIdx.x;
    const int total = S_LEN * 2 * NHEAD * 40;
    if (idx >= total) return;
    int i = idx % 40;
    int h = (idx / 40) % NHEAD;
    int w = (idx / (40 * NHEAD)) % 2;
    int s = idx / (40 * NHEAD * 2);
    const __half* p = qkv + (size_t)s * (3 * DMODEL) + w * DMODEL + h * HDIM;
    __half* dst = (w == 0 ? qh : kh) + (size_t)s * DMODEL + h * HDIM;
    float x1 = __half2float(p[i]);
    float x2 = __half2float(p[i + 40]);
    float f1 = rot[s * 40 + (i >> 1)];
    float f2 = rot[s * 40 + 20 + (i >> 1)];
    float c1, s1, c2, s2v;
    sincosf(f1, &s1, &c1);
    sincosf(f2, &s2v, &c2);
    dst[i]      = __float2half_rn(x1 * c1 - x2 * s1);
    dst[i + 40] = __float2half_rn(x2 * c2 + x1 * s2v);
}

// ---------------- V transpose: qkv fp16 [s][v:h*80+d] -> vth fp16 [h][d][s]
__global__ __launch_bounds__(256) void vtrans_kernel(
    const __half* __restrict__ qkv, __half* __restrict__ vth)
{
    __shared__ float t[HDIM][65];
    int s0 = blockIdx.x * 64;
    int h = blockIdx.y;
    int tid = threadIdx.x;
#pragma unroll
    for (int it = 0; it < 20; it++) {
        int idx = tid + it * 256;
        int sl = idx / 80, d = idx % 80;
        t[d][sl] = __half2float(
            qkv[(size_t)(s0 + sl) * (3 * DMODEL) + 2 * DMODEL + h * HDIM + d]);
    }
    __syncthreads();
#pragma unroll
    for (int it = 0; it < 20; it++) {
        int idx = tid + it * 256;
        int d = idx >> 6, sl = idx & 63;
        vth[(size_t)(h * HDIM + d) * S_LEN + s0 + sl] = __float2half_rn(t[d][sl]);
    }
}

// ---------------- fp16 flash attention (block-diag segments) --------------
#define AQSTR 176   // Q/K smem row stride, bytes
#define AVSTR 144   // VT & P smem row stride, bytes
#define AOFF_Q  0
#define AOFF_K0 11264
#define AOFF_K1 22528
#define AOFF_V0 33792
#define AOFF_V1 45312
#define ATTN_SMEM_BYTES 56832

__global__ __launch_bounds__(128, 1) void attn_h_kernel(
    const __half* __restrict__ qh, const __half* __restrict__ kh,
    const __half* __restrict__ vth, const int* __restrict__ cu,
    int nseg, __half* __restrict__ out)
{
    extern __shared__ __align__(16) char sm[];
    const uint32_t sb = smem_u32(sm);
    const int tid = threadIdx.x;
    const int warp = tid >> 5, lane = tid & 31;
    const int g = lane >> 2, t = lane & 3;
    const int h = blockIdx.y;
    const int q0 = blockIdx.x * 64;
    const int w16 = warp * 16;

    int start = 0, end = S_LEN;
    for (int i = 0; i < nseg; i++) {
        int a = cu[i], b = cu[i + 1];
        if (q0 >= a && q0 < b) { start = a; end = b; break; }
    }
    const int L = end - start;
    const int ntiles = (L + 63) >> 6;

    for (int i = tid; i < 640; i += 128) {
        int row = i / 10, c = i % 10;
        CP_ASYNC16(sb + AOFF_Q + (uint32_t)row * AQSTR + (uint32_t)c * 16,
                   (const char*)(qh + (size_t)(q0 + row) * DMODEL + h * HDIM) + c * 16);
    }
    CP_COMMIT();

    auto load_kv = [&](int stage, int k0) {
        const uint32_t kBase = sb + (stage ? AOFF_K1 : AOFF_K0);
        const uint32_t vBase = sb + (stage ? AOFF_V1 : AOFF_V0);
        for (int i = tid; i < 640; i += 128) {
            int row = i / 10, c = i % 10;
            int key = k0 + row;
            int src = start + (key < L ? key : L - 1);
            CP_ASYNC16(kBase + (uint32_t)row * AQSTR + (uint32_t)c * 16,
                       (const char*)(kh + (size_t)src * DMODEL + h * HDIM) + c * 16);
        }
        for (int i = tid; i < 640; i += 128) {
            int d = i >> 3, c = i & 7;
            int kk0 = k0 + c * 8;
            if (kk0 + 8 > L) kk0 = L - 8;
            CP_ASYNC16(vBase + (uint32_t)d * AVSTR + (uint32_t)c * 16,
                       (const char*)(vth + (size_t)(h * HDIM + d) * S_LEN + start + kk0));
        }
    };

    load_kv(0, 0);
    CP_COMMIT();
    CP_WAIT0();
    __syncthreads();

    uint32_t qf[5][4];
#pragma unroll
    for (int ks = 0; ks < 5; ks++) {
        const char* qp = sm + AOFF_Q + (w16 + g) * AQSTR + ks * 32 + 4 * t;
        qf[ks][0] = *(const uint32_t*)(qp);
        qf[ks][1] = *(const uint32_t*)(qp + 8 * AQSTR);
        qf[ks][2] = *(const uint32_t*)(qp + 16);
        qf[ks][3] = *(const uint32_t*)(qp + 8 * AQSTR + 16);
    }
    __syncthreads();

    if (1 < ntiles) {
        load_kv(1, 64);
    }
    CP_COMMIT();

    const float scale = 0.111803398875f;   // 1/sqrt(80)
    float m[2] = {-1e30f, -1e30f};
    float l[2] = {0.f, 0.f};
    float o[10][4];
#pragma unroll
    for (int nt = 0; nt < 10; nt++)
#pragma unroll
        for (int i = 0; i < 4; i++) o[nt][i] = 0.f;

    char* Pb = sm + AOFF_Q;

    for (int kt = 0; kt < ntiles; kt++) {
        if (kt > 0) {
            CP_WAIT0();
            __syncthreads();
            if (kt + 1 < ntiles) {
                load_kv((kt + 1) & 1, (kt + 1) * 64);
            }
            CP_COMMIT();
        }
        const char* K = sm + ((kt & 1) ? AOFF_K1 : AOFF_K0);
        const char* V = sm + ((kt & 1) ? AOFF_V1 : AOFF_V0);

        float s[8][4];
#pragma unroll
        for (int nt = 0; nt < 8; nt++)
#pragma unroll
            for (int i = 0; i < 4; i++) s[nt][i] = 0.f;
#pragma unroll
        for (int ks = 0; ks < 5; ks++) {
            uint32_t b[8][2];
#pragma unroll
            for (int nt = 0; nt < 8; nt++) {
                const char* kp = K + (nt * 8 + g) * AQSTR + ks * 32 + 4 * t;
                b[nt][0] = *(const uint32_t*)(kp);
                b[nt][1] = *(const uint32_t*)(kp + 16);
            }
#pragma unroll
            for (int nt = 0; nt < 8; nt++)
                mma_f16(s[nt], qf[ks], b[nt]);
        }

        const bool maskT = (kt == ntiles - 1) && (L & 63);
#pragma unroll
        for (int r = 0; r < 2; r++) {
            float mx = -1e30f;
#pragma unroll
            for (int nt = 0; nt < 8; nt++) {
                float v0 = s[nt][2 * r]     * scale;
                float v1 = s[nt][2 * r + 1] * scale;
                if (maskT) {
                    int col = kt * 64 + nt * 8 + 2 * t;
                    if (col >= L)     v0 = -1e30f;
                    if (col + 1 >= L) v1 = -1e30f;
                }
                s[nt][2 * r] = v0; s[nt][2 * r + 1] = v1;
                mx = fmaxf(mx, fmaxf(v0, v1));
            }
            mx = fmaxf(mx, __shfl_xor_sync(0xffffffffu, mx, 1));
            mx = fmaxf(mx, __shfl_xor_sync(0xffffffffu, mx, 2));
            float nm = fmaxf(m[r], mx);
            float fac = __expf(m[r] - nm);
            m[r] = nm;
            float sum = 0.f;
#pragma unroll
            for (int nt = 0; nt < 8; nt++) {
                float e0 = __expf(s[nt][2 * r] - nm);
                float e1 = __expf(s[nt][2 * r + 1] - nm);
                sum += e0 + e1;
                *(__half2*)(Pb + (w16 + g + 8 * r) * AVSTR + (nt * 8 + 2 * t) * 2) =
                    __halves2half2(__float2half_rn(e0), __float2half_rn(e1));
            }
            sum += __shfl_xor_sync(0xffffffffu, sum, 1);
            sum += __shfl_xor_sync(0xffffffffu, sum, 2);
            l[r] = l[r] * fac + sum;
#pragma unroll
            for (int nt = 0; nt < 10; nt++) {
                o[nt][2 * r] *= fac;
                o[nt][2 * r + 1] *= fac;
            }
        }
        __syncwarp();

#pragma unroll
        for (int ks = 0; ks < 4; ks++) {
            uint32_t a[4];
            const char* pp = Pb + (w16 + g) * AVSTR + ks * 32 + 4 * t;
            a[0] = *(const uint32_t*)(pp);
            a[1] = *(const uint32_t*)(pp + 8 * AVSTR);
            a[2] = *(const uint32_t*)(pp + 16);
            a[3] = *(const uint32_t*)(pp + 8 * AVSTR + 16);
            uint32_t b[10][2];
#pragma unroll
            for (int nt = 0; nt < 10; nt++) {
                const char* vp = V + (nt * 8 + g) * AVSTR + ks * 32 + 4 * t;
                b[nt][0] = *(const uint32_t*)(vp);
                b[nt][1] = *(const uint32_t*)(vp + 16);
            }
#pragma unroll
            for (int nt = 0; nt < 10; nt++)
                mma_f16(o[nt], a, b[nt]);
        }
        __syncwarp();
    }

#pragma unroll
    for (int r = 0; r < 2; r++) {
        float inv = 1.f / l[r];
        const int row = q0 + w16 + g + 8 * r;
#pragma unroll
        for (int nt = 0; nt < 10; nt++) {
            *(__half2*)(out + (size_t)row * DMODEL + h * HDIM + nt * 8 + 2 * t) =
                __halves2half2(__float2half_rn(o[nt][2 * r] * inv),
                               __float2half_rn(o[nt][2 * r + 1] * inv));
        }
    }
}

// ---------------- launch ----------------
static void* sym_addr(const void* sym)
{
    void* p = nullptr;
    cudaGetSymbolAddress(&p, sym);
    return p;
}

extern "C" void kernel_launch(void* const* d_in, const int* in_sizes, int n_in,
                              void* d_out, int out_size)
{
    const float* x        = (const float*)d_in[0];
    const float* rot      = (const float*)d_in[1];
    const float* ln1_s    = (const float*)d_in[2];
    const float* ln1_b    = (const float*)d_in[3];
    const float* ln2_s    = (const float*)d_in[4];
    const float* ln2_b    = (const float*)d_in[5];
    const float* qkv_w    = (const float*)d_in[6];
    const float* qkv_b    = (const float*)d_in[7];
    const float* proj_w   = (const float*)d_in[8];
    const float* proj_b   = (const float*)d_in[9];
    const float* fc1_w    = (const float*)d_in[10];
    const float* fc1_b    = (const float*)d_in[11];
    const float* fc2_w    = (const float*)d_in[12];
    const float* fc2_b    = (const float*)d_in[13];
    const int*   cu       = (const int*)d_in[14];
    float*       out      = (float*)d_out;
    const int    nseg     = in_sizes[14] - 1;

    __half* hh    = (__half*)sym_addr(g_hh);
    __half* qkvh  = (__half*)sym_addr(g_qkvh);
    __half* qh    = (__half*)sym_addr(g_qh);
    __half* kh    = (__half*)sym_addr(g_kh);
    __half* vth   = (__half*)sym_addr(g_vth);
    __half* attnh = (__half*)sym_addr(g_attnh);
    float*  x1    = (float*)sym_addr(g_x1);
    __half* ffh   = (__half*)sym_addr(g_ffh);
    __half* whqkv = (__half*)sym_addr(g_wh_qkv);
    __half* whprj = (__half*)sym_addr(g_wh_proj);
    __half* whfc1 = (__half*)sym_addr(g_wh_fc1);
    __half* whfc2 = (__half*)sym_addr(g_wh_fc2);

    cudaFuncSetAttribute(attn_h_kernel, cudaFuncAttributeMaxDynamicSharedMemorySize, ATTN_SMEM_BYTES);
    const int gemm_smem = NSTAGE * STG_BYTES;  // 81920
    cudaFuncSetAttribute(gemm_h<0, 0, 1>, cudaFuncAttributeMaxDynamicSharedMemorySize, gemm_smem);
    cudaFuncSetAttribute(gemm_h<0, 1, 0>, cudaFuncAttributeMaxDynamicSharedMemorySize, gemm_smem);
    cudaFuncSetAttribute(gemm_h<1, 0, 1>, cudaFuncAttributeMaxDynamicSharedMemorySize, gemm_smem);

    // 0) weight transpose+convert to fp16 [N][K]
    transpose_h64<<<dim3(3 * DMODEL / 64, DMODEL / 64), 256>>>(qkv_w, whqkv, DMODEL, 3 * DMODEL);
    transpose_h64<<<dim3(DMODEL / 64, DMODEL / 64), 256>>>(proj_w, whprj, DMODEL, DMODEL);
    transpose_h64<<<dim3(FFDIM / 64, DMODEL / 64), 256>>>(fc1_w, whfc1, DMODEL, FFDIM);
    transpose_h64<<<dim3(DMODEL / 64, FFDIM / 64), 256>>>(fc2_w, whfc2, FFDIM, DMODEL);

    // 1) LN1 (fp16 output)
    ln_kernel<<<S_LEN, 256>>>(x, ln1_s, ln1_b, hh);
    // 2) QKV = h @ qkv_w + b  (fp16 out)
    gemm_h<0, 0, 1><<<dim3(3 * DMODEL / 128, S_LEN / 128), 256, gemm_smem>>>(
        hh, whqkv, qkv_b, nullptr, qkvh, S_LEN, 3 * DMODEL, DMODEL);
    // 3) RoPE -> fp16 q/k; V -> fp16 transposed
    {
        int total = S_LEN * 2 * NHEAD * 40;
        rope_h_kernel<<<(total + 255) / 256, 256>>>(qkvh, rot, qh, kh);
        vtrans_kernel<<<dim3(S_LEN / 64, NHEAD), 256>>>(qkvh, vth);
    }
    // 4) fp16 flash attention -> fp16
    attn_h_kernel<<<dim3(S_LEN / 64, NHEAD), 128, ATTN_SMEM_BYTES>>>(qh, kh, vth, cu, nseg, attnh);
    // 5) x1 = x + attn @ proj_w + proj_b  (fp32 out)
    gemm_h<0, 1, 0><<<dim3(DMODEL / 128, S_LEN / 128), 256, gemm_smem>>>(
        attnh, whprj, proj_b, x, x1, S_LEN, DMODEL, DMODEL);
    // 6) LN2 (fp16 output)
    ln_kernel<<<S_LEN, 256>>>(x1, ln2_s, ln2_b, hh);
    // 7) ff = quick_gelu(h @ fc1_w + fc1_b)  (fp16 out)
    gemm_h<1, 0, 1><<<dim3(FFDIM / 128, S_LEN / 128), 256, gemm_smem>>>(
        hh, whfc1, fc1_b, nullptr, ffh, S_LEN, FFDIM, DMODEL);
    // 8) out = x1 + ff @ fc2_w + fc2_b  (fp32 out)
    gemm_h<0, 1, 0><<<dim3(DMODEL / 128, S_LEN / 128), 256, gemm_smem>>>(
        ffh, whfc2, fc2_b, x1, out, S_LEN, DMODEL, FFDIM);
}